// round 6
// baseline (speedup 1.0000x reference)
#include <cuda_runtime.h>

// HysteresisThresholding 2048x2048. Three kernels:
//  1) pack:  thresholds + byte-granular weak/strong mask stores (no warp ops)
//  2) flood: persistent band-local smem convergence; grid barrier with
//            embedded any-changed bit
//  3) final: active ? thin : 0, mask read as bytes

#define H_IMG 2048
#define W_IMG 2048
#define WX 64
#define N_WORDS (H_IMG * WX)
#define N_PIX (H_IMG * W_IMG)
#define N_BYTE (N_PIX / 8)
#define LOW_T 0.3f
#define HIGH_T 0.7f
#define MAX_PASS 256
#define MAX_ROWS 16
#define NT 1024

__device__ unsigned g_active[N_WORDS];
__device__ unsigned g_w1[N_WORDS];
__device__ unsigned g_w2[N_WORDS];
__device__ volatile unsigned g_arrive[256];
__device__ volatile unsigned g_release;

// ---------------- kernel 1: thresholds + byte mask pack ----------------
__global__ void __launch_bounds__(256)
pack_kernel(const float4* __restrict__ thin4, float* __restrict__ out) {
    int t = blockIdx.x * 256 + threadIdx.x;    // byte index: 8 pixels
    float4* low4  = (float4*)out;
    float4* high4 = (float4*)(out + N_PIX);

    float4 a = thin4[2 * t];
    float4 b = thin4[2 * t + 1];

    float4 lo, hi;
    lo.x = (a.x < LOW_T) ? 0.0f : a.x;  hi.x = (a.x < HIGH_T) ? 0.0f : a.x;
    lo.y = (a.y < LOW_T) ? 0.0f : a.y;  hi.y = (a.y < HIGH_T) ? 0.0f : a.y;
    lo.z = (a.z < LOW_T) ? 0.0f : a.z;  hi.z = (a.z < HIGH_T) ? 0.0f : a.z;
    lo.w = (a.w < LOW_T) ? 0.0f : a.w;  hi.w = (a.w < HIGH_T) ? 0.0f : a.w;
    low4[2 * t] = lo;  high4[2 * t] = hi;
    lo.x = (b.x < LOW_T) ? 0.0f : b.x;  hi.x = (b.x < HIGH_T) ? 0.0f : b.x;
    lo.y = (b.y < LOW_T) ? 0.0f : b.y;  hi.y = (b.y < HIGH_T) ? 0.0f : b.y;
    lo.z = (b.z < LOW_T) ? 0.0f : b.z;  hi.z = (b.z < HIGH_T) ? 0.0f : b.z;
    lo.w = (b.w < LOW_T) ? 0.0f : b.w;  hi.w = (b.w < HIGH_T) ? 0.0f : b.w;
    low4[2 * t + 1] = lo;  high4[2 * t + 1] = hi;

    unsigned wk = (a.x >= LOW_T  ?   1u : 0u) | (a.y >= LOW_T  ?   2u : 0u)
                | (a.z >= LOW_T  ?   4u : 0u) | (a.w >= LOW_T  ?   8u : 0u)
                | (b.x >= LOW_T  ?  16u : 0u) | (b.y >= LOW_T  ?  32u : 0u)
                | (b.z >= LOW_T  ?  64u : 0u) | (b.w >= LOW_T  ? 128u : 0u);
    unsigned ac = (a.x >= HIGH_T ?   1u : 0u) | (a.y >= HIGH_T ?   2u : 0u)
                | (a.z >= HIGH_T ?   4u : 0u) | (a.w >= HIGH_T ?   8u : 0u)
                | (b.x >= HIGH_T ?  16u : 0u) | (b.y >= HIGH_T ?  32u : 0u)
                | (b.z >= HIGH_T ?  64u : 0u) | (b.w >= HIGH_T ? 128u : 0u);

    int r    = t >> 8;       // image row
    int bcol = t & 255;      // byte column within row
    unsigned m1 = 0xFFu, m2 = 0xFFu;
    if (r < 1 || r > H_IMG - 3) m1 = 0u;
    else if (bcol == 0)   m1 = 0xFEu;
    else if (bcol == 255) m1 = 0x3Fu;
    if (r < 2 || r > H_IMG - 4) m2 = 0u;
    else if (bcol == 0)   m2 = 0xFCu;
    else if (bcol == 255) m2 = 0x1Fu;

    ((unsigned char*)g_w1)[t]     = (unsigned char)(wk & m1);
    ((unsigned char*)g_w2)[t]     = (unsigned char)(wk & m2);
    ((unsigned char*)g_active)[t] = (unsigned char)ac;

    if (blockIdx.x == 0) {
        if (threadIdx.x < 256) g_arrive[threadIdx.x] = 0u;
        if (threadIdx.x == 0) g_release = 0u;
    }
}

// ---------------- kernel 2: band-local flood fill ----------------
__global__ void __launch_bounds__(NT, 1)
flood_kernel(int rows_per, unsigned nblocks) {
    __shared__ unsigned s_act[(MAX_ROWS + 4) * WX];
    __shared__ unsigned s_w1[MAX_ROWS * WX];
    __shared__ unsigned s_w2[MAX_ROWS * WX];
    __shared__ unsigned s_any;

    const int tid = threadIdx.x;
    const int bid = blockIdx.x;
    const int r0  = bid * rows_per;
    const int nrows  = max(0, min(H_IMG - r0, rows_per));
    const int nwords = nrows * WX;

    for (int i = tid; i < (MAX_ROWS + 4) * WX; i += NT) s_act[i] = 0u;
    if (tid < nwords) {
        s_w1[tid] = g_w1[r0 * WX + tid];
        s_w2[tid] = g_w2[r0 * WX + tid];
        s_act[((tid >> 6) + 2) * WX + (tid & 63)] = g_active[r0 * WX + tid];
    }
    __syncthreads();

    unsigned gen = 0;
    for (int pass = 0; pass < MAX_PASS; pass++) {
        // reload 4 halo rows
        for (int i = tid; i < 4 * WX; i += NT) {
            int hr = i >> 6, wx = i & 63;
            int gr = (hr < 2) ? (r0 - 2 + hr) : (r0 + nrows + (hr - 2));
            int sr = (hr < 2) ? hr : (nrows + hr);
            unsigned v = 0u;
            if (gr >= 0 && gr < H_IMG) v = __ldcg(&g_active[gr * WX + wx]);
            s_act[sr * WX + wx] = v;
        }
        __syncthreads();

        bool band_changed = false;
        for (;;) {
            bool ch = false;
            if (tid < nwords) {
                int wx = tid & 63;
                int sr = (tid >> 6) + 2;
                unsigned c  = s_act[sr * WX + wx];
                unsigned w1 = s_w1[tid];
                unsigned w2 = s_w2[tid];
                unsigned todo = (w1 | w2) & ~c;
                if (todo) {
                    auto S = [&](int r_, int x_) -> unsigned {
                        return ((unsigned)x_ < (unsigned)WX) ? s_act[r_ * WX + x_] : 0u;
                    };
                    unsigned l  = S(sr, wx - 1),      rr = S(sr, wx + 1);
                    unsigned u1 = S(sr - 1, wx), u1l = S(sr - 1, wx - 1), u1r = S(sr - 1, wx + 1);
                    unsigned d1 = S(sr + 1, wx), d1l = S(sr + 1, wx - 1), d1r = S(sr + 1, wx + 1);
                    unsigned conn1 =
                          u1 | __funnelshift_l(u1l, u1, 1) | __funnelshift_r(u1, u1r, 1)
                        |      __funnelshift_l(l,   c,  1) | __funnelshift_r(c,  rr,  1)
                        | d1 | __funnelshift_l(d1l, d1, 1) | __funnelshift_r(d1, d1r, 1);
                    unsigned nw = c | (w1 & conn1);
                    if (w2 & ~nw) {
                        unsigned u2 = S(sr - 2, wx), u2l = S(sr - 2, wx - 1), u2r = S(sr - 2, wx + 1);
                        unsigned d2 = S(sr + 2, wx), d2l = S(sr + 2, wx - 1), d2r = S(sr + 2, wx + 1);
                        unsigned conn2 =
                              u2 | __funnelshift_l(u2l, u2, 2) | __funnelshift_r(u2, u2r, 2)
                            |      __funnelshift_l(l,   c,  2) | __funnelshift_r(c,  rr,  2)
                            | d2 | __funnelshift_l(d2l, d2, 2) | __funnelshift_r(d2, d2r, 2);
                        nw |= w2 & conn2;
                    }
                    #pragma unroll
                    for (int k = 0; k < 5; k++) {
                        unsigned sp = nw;
                        nw |= (w1 & ((sp << 1) | (sp >> 1)))
                            | (w2 & ((sp << 2) | (sp >> 2)));
                    }
                    if (nw != c) { s_act[sr * WX + wx] = nw; ch = true; }
                }
            }
            if (!__syncthreads_or(ch ? 1 : 0)) break;
            band_changed = true;
        }

        if (band_changed && tid < nwords)
            __stcg(&g_active[r0 * WX + tid],
                   s_act[((tid >> 6) + 2) * WX + (tid & 63)]);

        // -------- grid barrier with embedded any-changed --------
        gen++;
        __syncthreads();
        if (tid == 0) {
            __threadfence();
            g_arrive[bid] = (gen << 1) | (band_changed ? 1u : 0u);
        }
        if (bid == 0) {
            unsigned myany = 0u;
            if (tid < (int)nblocks) {
                unsigned v;
                while (((v = g_arrive[tid]) >> 1) < gen) __nanosleep(32);
                myany = v & 1u;
            }
            unsigned any = __syncthreads_or(myany);
            if (tid == 0) { __threadfence(); g_release = (gen << 1) | any; }
        }
        if (tid == 0) {
            unsigned v;
            while (((v = g_release) >> 1) < gen) __nanosleep(32);
            s_any = v & 1u;
            __threadfence();
        }
        __syncthreads();
        if (!s_any) break;
    }
}

// ---------------- kernel 3: final output ----------------
__global__ void __launch_bounds__(256)
final_kernel(const float4* __restrict__ thin4, float* __restrict__ out) {
    int t = blockIdx.x * 256 + threadIdx.x;    // byte index: 8 pixels
    float4* final4 = (float4*)(out + 2 * N_PIX);
    unsigned bits = ((const unsigned char*)g_active)[t];
    float4 a = thin4[2 * t];
    float4 b = thin4[2 * t + 1];
    float4 f;
    f.x = (bits &   1u) ? a.x : 0.0f;
    f.y = (bits &   2u) ? a.y : 0.0f;
    f.z = (bits &   4u) ? a.z : 0.0f;
    f.w = (bits &   8u) ? a.w : 0.0f;
    final4[2 * t] = f;
    f.x = (bits &  16u) ? b.x : 0.0f;
    f.y = (bits &  32u) ? b.y : 0.0f;
    f.z = (bits &  64u) ? b.z : 0.0f;
    f.w = (bits & 128u) ? b.w : 0.0f;
    final4[2 * t + 1] = f;
}

extern "C" void kernel_launch(void* const* d_in, const int* in_sizes, int n_in,
                              void* d_out, int out_size) {
    const float* thin = (const float*)d_in[0];
    float* out = (float*)d_out;
    (void)in_sizes; (void)n_in; (void)out_size;

    int dev = 0;
    cudaGetDevice(&dev);
    int nsm = 0;
    cudaDeviceGetAttribute(&nsm, cudaDevAttrMultiProcessorCount, dev);
    if (nsm <= 0) nsm = 148;

    int rows_per = (H_IMG + nsm - 1) / nsm;
    if (rows_per > MAX_ROWS) rows_per = MAX_ROWS;
    unsigned fgrid = (unsigned)((H_IMG + rows_per - 1) / rows_per);

    pack_kernel<<<N_BYTE / 256, 256>>>((const float4*)thin, out);
    flood_kernel<<<fgrid, NT>>>(rows_per, fgrid);
    final_kernel<<<N_BYTE / 256, 256>>>((const float4*)thin, out);
}